// round 3
// baseline (speedup 1.0000x reference)
#include <cuda_runtime.h>
#include <cstdint>

#define N_POS 4096
#define N_NEG 4096
#define N_NEU 2048
#define N_ROW (N_POS + N_NEG)            // 8192
#define DIM   512

#define THREADS 128
#define WARPS_PER_BLK (THREADS / 32)     // 4
#define ROW_BLOCKS (N_ROW / WARPS_PER_BLK)                 // 2048
#define NEU_BLOCKS ((N_NEU + THREADS - 1) / THREADS)       // 16
#define GRID (ROW_BLOCKS + NEU_BLOCKS)                     // 2064

#define SCALE (0.5f / (float)(N_POS + N_NEG + N_NEU))

__device__ float    g_accum = 0.0f;
__device__ unsigned g_count = 0u;

__device__ __forceinline__ float pick(const float4& v, int off) {
    float a = (off & 2) ? v.z : v.x;
    float b = (off & 2) ? v.w : v.y;
    return (off & 1) ? b : a;
}

__global__ __launch_bounds__(THREADS) void dcl_kernel(
    const float* __restrict__ emb,
    const int* __restrict__ pos_ids, const int* __restrict__ pos_dims,
    const int* __restrict__ neg_ids, const int* __restrict__ neg_dims,
    const int* __restrict__ neu_ids, const int* __restrict__ neu_dims,
    float* __restrict__ out)
{
    const int lane = threadIdx.x & 31;
    const int warp = threadIdx.x >> 5;

    float local = 0.0f;

    if (blockIdx.x < ROW_BLOCKS) {
        // ---- pos/neg: one row-constraint per warp ----
        int w = blockIdx.x * WARPS_PER_BLK + warp;       // 0..8191
        bool positive = (w < N_POS);
        int idx = positive ? w : (w - N_POS);
        int id  = positive ? __ldg(pos_ids  + idx) : __ldg(neg_ids  + idx);
        int dim = positive ? __ldg(pos_dims + idx) : __ldg(neg_dims + idx);

        const float4* row = reinterpret_cast<const float4*>(emb + (size_t)id * DIM);

        // 4 independent LDG.128 front-batched (2KB per warp in flight)
        float4 a0 = row[lane +  0];
        float4 a1 = row[lane + 32];
        float4 a2 = row[lane + 64];
        float4 a3 = row[lane + 96];

        float s = fabsf(a0.x)+fabsf(a0.y)+fabsf(a0.z)+fabsf(a0.w)
                + fabsf(a1.x)+fabsf(a1.y)+fabsf(a1.z)+fabsf(a1.w)
                + fabsf(a2.x)+fabsf(a2.y)+fabsf(a2.z)+fabsf(a2.w)
                + fabsf(a3.x)+fabsf(a3.y)+fabsf(a3.z)+fabsf(a3.w);

        // target-dim value: owning lane contributes, others 0
        float t = 0.0f;
        int e = dim >> 2;                 // float4 index 0..127
        if ((e & 31) == lane) {
            float4 v = (e < 32) ? a0 : (e < 64) ? a1 : (e < 96) ? a2 : a3;
            t = pick(v, dim & 3);
        }

        #pragma unroll
        for (int o = 16; o; o >>= 1) {
            s += __shfl_xor_sync(0xFFFFFFFFu, s, o);
            t += __shfl_xor_sync(0xFFFFFFFFu, t, o);
        }

        if (lane == 0) {
            float at = fabsf(t);
            float sl = positive
                ? ((t <= 0.0f) ? (at + 0.1f) : (-0.1f * t))
                : ((t >= 0.0f) ? (at + 0.1f) : (-0.1f * at));
            local = sl + (s - at) * (0.1f / (float)(DIM - 1));
        }
    } else {
        // ---- neutral: one element per thread ----
        int i = (blockIdx.x - ROW_BLOCKS) * THREADS + threadIdx.x;
        if (i < N_NEU) {
            int id  = __ldg(neu_ids + i);
            int dim = __ldg(neu_dims + i);
            local = 2.0f * fabsf(__ldg(emb + (size_t)id * DIM + dim));
        }
    }

    // ---- block reduce (4 warps) ----
    #pragma unroll
    for (int o = 16; o; o >>= 1)
        local += __shfl_xor_sync(0xFFFFFFFFu, local, o);

    __shared__ float sh[WARPS_PER_BLK];
    if (lane == 0) sh[warp] = local;
    __syncthreads();

    if (threadIdx.x == 0) {
        float v = sh[0] + sh[1] + sh[2] + sh[3];
        atomicAdd(&g_accum, v);
        __threadfence();
        unsigned n = atomicAdd(&g_count, 1u);
        if (n == (unsigned)(GRID - 1)) {
            // last block: finalize and reset scratch for next graph replay
            __threadfence();
            float total = atomicExch(&g_accum, 0.0f);
            atomicExch(&g_count, 0u);
            out[0] = total * SCALE;
        }
    }
}

extern "C" void kernel_launch(void* const* d_in, const int* in_sizes, int n_in,
                              void* d_out, int out_size)
{
    const float* emb      = (const float*)d_in[0];
    const int*   pos_ids  = (const int*)d_in[1];
    const int*   pos_dims = (const int*)d_in[2];
    const int*   neg_ids  = (const int*)d_in[3];
    const int*   neg_dims = (const int*)d_in[4];
    const int*   neu_ids  = (const int*)d_in[5];
    const int*   neu_dims = (const int*)d_in[6];

    dcl_kernel<<<GRID, THREADS>>>(
        emb, pos_ids, pos_dims, neg_ids, neg_dims, neu_ids, neu_dims,
        (float*)d_out);
}

// round 5
// speedup vs baseline: 1.2007x; 1.2007x over previous
#include <cuda_runtime.h>
#include <cstdint>

#define N_POS 4096
#define N_NEG 4096
#define N_NEU 2048
#define N_ROW (N_POS + N_NEG)            // 8192
#define DIM   512

#define THREADS 256
#define WARPS_PER_BLK (THREADS / 32)     // 8
#define ROW_BLOCKS (N_ROW / WARPS_PER_BLK)                 // 1024
#define NEU_BLOCKS ((N_NEU + THREADS - 1) / THREADS)       // 8
#define GRID (ROW_BLOCKS + NEU_BLOCKS)                     // 1032

#define SCALE (0.5f / (float)(N_POS + N_NEG + N_NEU))

__device__ float    g_accum = 0.0f;
__device__ unsigned g_count = 0u;

__device__ __forceinline__ float pick(const float4& v, int off) {
    float a = (off & 2) ? v.z : v.x;
    float b = (off & 2) ? v.w : v.y;
    return (off & 1) ? b : a;
}

__device__ __forceinline__ float warp_sum(float x) {
    #pragma unroll
    for (int o = 16; o; o >>= 1)
        x += __shfl_xor_sync(0xFFFFFFFFu, x, o);
    return x;
}

__global__ __launch_bounds__(THREADS) void dcl_kernel(
    const float* __restrict__ emb,
    const int* __restrict__ pos_ids, const int* __restrict__ pos_dims,
    const int* __restrict__ neg_ids, const int* __restrict__ neg_dims,
    const int* __restrict__ neu_ids, const int* __restrict__ neu_dims,
    float* __restrict__ out)
{
    const int lane = threadIdx.x & 31;
    const int warp = threadIdx.x >> 5;

    float local = 0.0f;

    if (blockIdx.x < ROW_BLOCKS) {
        // ---- pos/neg: one row-constraint per warp ----
        int w = blockIdx.x * WARPS_PER_BLK + warp;       // 0..8191
        bool positive = (w < N_POS);
        int idx = positive ? w : (w - N_POS);
        int id  = positive ? __ldg(pos_ids  + idx) : __ldg(neg_ids  + idx);
        int dim = positive ? __ldg(pos_dims + idx) : __ldg(neg_dims + idx);

        const float4* row = reinterpret_cast<const float4*>(emb + (size_t)id * DIM);

        // 4 independent LDG.128 front-batched (2KB per warp in flight)
        float4 a0 = row[lane +  0];
        float4 a1 = row[lane + 32];
        float4 a2 = row[lane + 64];
        float4 a3 = row[lane + 96];

        float s = fabsf(a0.x)+fabsf(a0.y)+fabsf(a0.z)+fabsf(a0.w)
                + fabsf(a1.x)+fabsf(a1.y)+fabsf(a1.z)+fabsf(a1.w)
                + fabsf(a2.x)+fabsf(a2.y)+fabsf(a2.z)+fabsf(a2.w)
                + fabsf(a3.x)+fabsf(a3.y)+fabsf(a3.z)+fabsf(a3.w);

        // target-dim value: dim is warp-uniform, so every lane knows the
        // owning lane; each lane computes its candidate, one shfl broadcasts.
        int e  = dim >> 2;                // float4 index 0..127
        int ri = e >> 5;                  // which register a0..a3
        float4 vsel = (ri == 0) ? a0 : (ri == 1) ? a1 : (ri == 2) ? a2 : a3;
        float cand = pick(vsel, dim & 3);
        float t = __shfl_sync(0xFFFFFFFFu, cand, e & 31);

        // single butterfly for s (t needs no reduction)
        s = warp_sum(s);

        if (lane == 0) {
            float at = fabsf(t);
            float sl = positive
                ? ((t <= 0.0f) ? (at + 0.1f) : (-0.1f * t))
                : ((t >= 0.0f) ? (at + 0.1f) : (-0.1f * at));
            local = sl + (s - at) * (0.1f / (float)(DIM - 1));
        }
    } else {
        // ---- neutral: one element per thread ----
        int i = (blockIdx.x - ROW_BLOCKS) * THREADS + threadIdx.x;
        if (i < N_NEU) {
            int id  = __ldg(neu_ids + i);
            int dim = __ldg(neu_dims + i);
            local = 2.0f * fabsf(__ldg(emb + (size_t)id * DIM + dim));
        }
        local = warp_sum(local);
        if (lane != 0) local = 0.0f;
    }

    // ---- block reduce (8 warps, only lane0 of each holds a value) ----
    __shared__ float sh[WARPS_PER_BLK];
    if (lane == 0) sh[warp] = local;
    __syncthreads();

    if (threadIdx.x == 0) {
        float v = sh[0] + sh[1] + sh[2] + sh[3]
                + sh[4] + sh[5] + sh[6] + sh[7];
        atomicAdd(&g_accum, v);
        __threadfence();
        unsigned n = atomicAdd(&g_count, 1u);
        if (n == (unsigned)(GRID - 1)) {
            // last block: finalize and reset scratch for next graph replay
            __threadfence();
            float total = atomicExch(&g_accum, 0.0f);
            atomicExch(&g_count, 0u);
            out[0] = total * SCALE;
        }
    }
}

extern "C" void kernel_launch(void* const* d_in, const int* in_sizes, int n_in,
                              void* d_out, int out_size)
{
    const float* emb      = (const float*)d_in[0];
    const int*   pos_ids  = (const int*)d_in[1];
    const int*   pos_dims = (const int*)d_in[2];
    const int*   neg_ids  = (const int*)d_in[3];
    const int*   neg_dims = (const int*)d_in[4];
    const int*   neu_ids  = (const int*)d_in[5];
    const int*   neu_dims = (const int*)d_in[6];

    dcl_kernel<<<GRID, THREADS>>>(
        emb, pos_ids, pos_dims, neg_ids, neg_dims, neu_ids, neu_dims,
        (float*)d_out);
}